// round 14
// baseline (speedup 1.0000x reference)
#include <cuda_runtime.h>
#include <cuda_bf16.h>
#include <math.h>

#define NEG 0.01f
typedef __nv_bfloat16 bf16;

// ---------------------------------------------------------------------------
// Scratch (allocation-free rule: __device__ globals)
// g_hHi/g_hLo layout: [64 kb][16384 b][64]  (k-block major, so kernC's
//   per-stage A slice [kb][m0:m0+128][0:64] is one contiguous 16KB run)
// g_wHi/g_wLo layout: [64 kb][80 o][64]
// ---------------------------------------------------------------------------
__device__ __align__(16) float g_K[4 * 64 * 64];
__device__ int g_band[4];
__device__ __align__(16) bf16 g_wHi[64 * 80 * 64];
__device__ __align__(16) bf16 g_wLo[64 * 80 * 64];
__device__ __align__(16) bf16 g_hHi[(size_t)64 * 16384 * 64];
__device__ __align__(16) bf16 g_hLo[(size_t)64 * 16384 * 64];

// ---------------------------------------------------------------------------
// Kernel K: build 4 L1-normalized gaussian mixing matrices + band radii
// ---------------------------------------------------------------------------
__global__ void kernK(const float* __restrict__ s0, const float* __restrict__ s1,
                      const float* __restrict__ s2, const float* __restrict__ s3) {
    int t = threadIdx.x;
    int l = t >> 6, i = t & 63;
    float sg = (l == 0) ? s0[0] : (l == 1) ? s1[0] : (l == 2) ? s2[0] : s3[0];
    float denom = 2.0f * sg * sg;
    float sum = 0.0f;
    for (int j = 0; j < 64; j++) {
        float d = (float)(i - j);
        sum += expf(-(d * d) / denom);
    }
    sum = fmaxf(sum, 1e-12f);
    for (int j = 0; j < 64; j++) {
        float d = (float)(i - j);
        g_K[(l * 64 + i) * 64 + j] = expf(-(d * d) / denom) / sum;
    }
    if (i == 0) {
        float rr = sqrtf(fmaxf(denom, 0.0f) * 18.5f);
        int R = (int)rr + 1;
        if (R > 63) R = 63;
        g_band[l] = R;
    }
}

// ---------------------------------------------------------------------------
// Kernel T: split wm0 [80][4096] fp32 -> bf16 hi/lo in [kb][o][64] layout
// ---------------------------------------------------------------------------
__global__ void kernT(const float* __restrict__ wm0) {
    int idx = blockIdx.x * blockDim.x + threadIdx.x;
    if (idx >= 80 * 4096) return;
    int o = idx >> 12, k = idx & 4095;
    int kb = k >> 6, c = k & 63;
    float v = wm0[idx];
    bf16 hi = __float2bfloat16_rn(v);
    bf16 lo = __float2bfloat16_rn(v - __bfloat162float(hi));
    int dst = kb * 5120 + o * 64 + c;
    g_wHi[dst] = hi;
    g_wLo[dst] = lo;
}

// ---------------------------------------------------------------------------
// mma / mbarrier / bulk-copy helpers
// ---------------------------------------------------------------------------
__device__ __forceinline__ void ldx4(unsigned r[4], const bf16* p) {
    unsigned a = (unsigned)__cvta_generic_to_shared(p);
    asm volatile("ldmatrix.sync.aligned.m8n8.x4.shared.b16 {%0,%1,%2,%3}, [%4];"
                 : "=r"(r[0]), "=r"(r[1]), "=r"(r[2]), "=r"(r[3]) : "r"(a));
}
__device__ __forceinline__ void ldx2(unsigned r[2], const bf16* p) {
    unsigned a = (unsigned)__cvta_generic_to_shared(p);
    asm volatile("ldmatrix.sync.aligned.m8n8.x2.shared.b16 {%0,%1}, [%2];"
                 : "=r"(r[0]), "=r"(r[1]) : "r"(a));
}
__device__ __forceinline__ void ldx2t(unsigned r[2], const bf16* p) {
    unsigned a = (unsigned)__cvta_generic_to_shared(p);
    asm volatile("ldmatrix.sync.aligned.m8n8.x2.trans.shared.b16 {%0,%1}, [%2];"
                 : "=r"(r[0]), "=r"(r[1]) : "r"(a));
}
__device__ __forceinline__ void hmma(float c[4], const unsigned a[4], const unsigned b[2]) {
    asm volatile("mma.sync.aligned.m16n8k16.row.col.f32.bf16.bf16.f32 "
                 "{%0,%1,%2,%3}, {%4,%5,%6,%7}, {%8,%9}, {%0,%1,%2,%3};"
                 : "+f"(c[0]), "+f"(c[1]), "+f"(c[2]), "+f"(c[3])
                 : "r"(a[0]), "r"(a[1]), "r"(a[2]), "r"(a[3]), "r"(b[0]), "r"(b[1]));
}
__device__ __forceinline__ float lrelu(float v) { return v > 0.f ? v : v * NEG; }
__device__ __forceinline__ void bsplit(bf16* hp, bf16* lp, float v) {
    bf16 h = __float2bfloat16_rn(v);
    *hp = h;
    *lp = __float2bfloat16_rn(v - __bfloat162float(h));
}
__device__ __forceinline__ void bsplit2(bf16* hp, bf16* lp, float v0, float v1) {
    __nv_bfloat162 h = __floats2bfloat162_rn(v0, v1);
    float r0 = v0 - __bfloat162float(h.x);
    float r1 = v1 - __bfloat162float(h.y);
    __nv_bfloat162 l = __floats2bfloat162_rn(r0, r1);
    *(__nv_bfloat162*)hp = h;
    *(__nv_bfloat162*)lp = l;
}
__device__ __forceinline__ void mb_init(unsigned a, unsigned cnt) {
    asm volatile("mbarrier.init.shared.b64 [%0], %1;" :: "r"(a), "r"(cnt) : "memory");
}
__device__ __forceinline__ void mb_expect(unsigned a, unsigned tx) {
    asm volatile("mbarrier.arrive.expect_tx.shared.b64 _, [%0], %1;" :: "r"(a), "r"(tx) : "memory");
}
__device__ __forceinline__ void mb_wait(unsigned a, unsigned ph) {
    unsigned done;
    do {
        asm volatile("{\n\t.reg .pred p;\n\t"
                     "mbarrier.try_wait.parity.acquire.cta.shared::cta.b64 p, [%1], %2, 0x989680;\n\t"
                     "selp.b32 %0, 1, 0, p;\n\t}"
                     : "=r"(done) : "r"(a), "r"(ph) : "memory");
    } while (!done);
}
__device__ __forceinline__ void bulk128(bf16* dst, const bf16* src, unsigned mb) {
    unsigned d = (unsigned)__cvta_generic_to_shared(dst);
    asm volatile("cp.async.bulk.shared::cluster.global.mbarrier::complete_tx::bytes "
                 "[%0], [%1], %2, [%3];"
                 :: "r"(d), "l"(src), "r"(128u), "r"(mb) : "memory");
}

// Accumulate NT 16x8 tiles sharing one A-fragment load per k-tile.
// All 3 split terms (AhBh + AhBl + AlBh) go into ONE accumulator per tile.
template <bool BT, int NT>
__device__ __forceinline__ void tileN(float (*acc)[4],
                                      const bf16* Ah, const bf16* Al, int lda, int m0,
                                      const bf16* Bh, const bf16* Bl, int ldb, int n0,
                                      int ktlo, int kthi, int lane) {
    const int arow = m0 + (lane & 7) + ((lane >> 3) & 1) * 8;
    const int acol = (lane >> 4) * 8;
    for (int kt = ktlo; kt <= kthi; kt++) {
        const int kc = kt * 16;
        unsigned ah[4], al[4];
        ldx4(ah, Ah + arow * lda + kc + acol);
        ldx4(al, Al + arow * lda + kc + acol);
        #pragma unroll
        for (int n = 0; n < NT; n++) {
            const int nn = n0 + n * 8;
            unsigned bh[2], bl[2];
            if (BT) {
                const int br = kc + (lane & 15);
                ldx2t(bh, Bh + br * ldb + nn);
                ldx2t(bl, Bl + br * ldb + nn);
            } else {
                const int br = nn + (lane & 7);
                const int bc = kc + ((lane >> 3) & 1) * 8;
                ldx2(bh, Bh + br * ldb + bc);
                ldx2(bl, Bl + br * ldb + bc);
            }
            hmma(acc[n], ah, bh);
            hmma(acc[n], ah, bl);
            hmma(acc[n], al, bh);
        }
    }
}

// ---------------------------------------------------------------------------
// Kernel G (tensor-core): fused 4-layer gaussian stack.
// 512 threads / 16 warps; block = 16 samples as 8 groups of S=2; register
// prefetch of next group's x. Warp-tiles widened (NT) for A-fragment reuse.
// ---------------------------------------------------------------------------
#define OKH   0
#define OKL   18432
#define OR1H  36864
#define OR1L  46080
#define OR2   55296
#define OR3   65536
#define OW0H  75776
#define OW0L  76352
#define OW1H  76928
#define OW1L  77184
#define OW2H  77440
#define OW2L  77952
#define OW3H  78464
#define OW3L  81024
#define OHALVES 83584
#define KG_SMEM_BYTES (OHALVES * 2 + 480)

__global__ __launch_bounds__(512) void kernG(
    const float* __restrict__ x,
    const float* __restrict__ w0, const float* __restrict__ b0,
    const float* __restrict__ w1, const float* __restrict__ b1,
    const float* __restrict__ w2, const float* __restrict__ b2,
    const float* __restrict__ w3, const float* __restrict__ b3)
{
    extern __shared__ __align__(16) bf16 sm[];
    float* sBias = (float*)(sm + OHALVES);   // b0@0, b1@8, b2@24, b3@56

    const int tid = threadIdx.x;
    const int lane = tid & 31;
    const int warp = tid >> 5;
    const int R0 = g_band[0], R1b = g_band[1], R2b = g_band[2], R3b = g_band[3];

    const float4* xb4 = (const float4*)x;
    float4 xr[4];
    {
        const int gb = blockIdx.x * 16;
        #pragma unroll
        for (int k = 0; k < 4; k++) {
            int idx = tid + k * 512;
            xr[k] = xb4[(size_t)(gb + (idx >> 10)) * 1024 + (idx & 1023)];
        }
    }

    // ---- one-time staging ----
    for (int idx = tid; idx < 16384; idx += 512) {
        int l = idx >> 12, i = (idx >> 6) & 63, j = idx & 63;
        bsplit(sm + OKH + l * 4608 + i * 72 + j, sm + OKL + l * 4608 + i * 72 + j, g_K[idx]);
    }
    if (tid < 512) {
        int o = tid >> 6, c = tid & 63;
        bsplit(sm + OW0H + o * 72 + c, sm + OW0L + o * 72 + c, w0[tid]);
    }
    if (tid < 256) {
        int o = tid >> 4, c = tid & 15;
        float v = (c < 8) ? w1[o * 8 + c] : 0.f;
        bsplit(sm + OW1H + o * 16 + c, sm + OW1L + o * 16 + c, v);
    }
    if (tid < 512) {
        int o = tid >> 4, c = tid & 15;
        bsplit(sm + OW2H + o * 16 + c, sm + OW2L + o * 16 + c, w2[tid]);
    }
    for (int idx = tid; idx < 2048; idx += 512) {
        int o = idx >> 5, c = idx & 31;
        bsplit(sm + OW3H + o * 40 + c, sm + OW3L + o * 40 + c, w3[idx]);
    }
    if (tid < 8) sBias[tid] = b0[tid];
    else if (tid >= 32 && tid < 48) sBias[8 + tid - 32] = b1[tid - 32];
    else if (tid >= 64 && tid < 96) sBias[24 + tid - 64] = b2[tid - 64];
    else if (tid >= 128 && tid < 192) sBias[56 + tid - 128] = b3[tid - 128];
    __syncthreads();

    const int erow = lane >> 2;
    const int ecol = (lane & 3) * 2;

    for (int g = 0; g < 8; g++) {
        const int gb = blockIdx.x * 16 + g * 2;

        // ---- split prefetched X regs -> R1 (A-layout [s*64+h][72]) ----
        #pragma unroll
        for (int k = 0; k < 4; k++) {
            int idx = tid + k * 512;
            int s = idx >> 10, rem = idx & 1023;
            int h = rem >> 4, c4 = rem & 15;
            int o = (s * 64 + h) * 72 + c4 * 4;
            bsplit2(sm + OR1H + o, sm + OR1L + o, xr[k].x, xr[k].y);
            bsplit2(sm + OR1H + o + 2, sm + OR1L + o + 2, xr[k].z, xr[k].w);
        }
        __syncthreads();

        if (g < 7) {
            const int gbn = gb + 2;
            #pragma unroll
            for (int k = 0; k < 4; k++) {
                int idx = tid + k * 512;
                xr[k] = xb4[(size_t)(gbn + (idx >> 10)) * 1024 + (idx & 1023)];
            }
        }

        // ---- G0: L0 wmult  M=128 K=64 N=8 : X@W0 + b0 -> R2.B [h][s*8+c]
        if (warp < 8) {
            const int m0 = warp * 16;
            float acc[1][4] = {};
            tileN<false, 1>(acc, sm + OR1H, sm + OR1L, 72, m0,
                            sm + OW0H, sm + OW0L, 72, 0, 0, 3, lane);
            float v[4];
            #pragma unroll
            for (int cr = 0; cr < 4; cr++)
                v[cr] = acc[0][cr] + sBias[ecol + (cr & 1)];
            int r0 = m0 + erow;
            int s = r0 >> 6;
            int o0 = (r0 & 63) * 72 + s * 8 + ecol;
            int o1 = ((r0 + 8) & 63) * 72 + s * 8 + ecol;
            bsplit2(sm + OR2 + o0, sm + OR2 + 4608 + o0, v[0], v[1]);
            bsplit2(sm + OR2 + o1, sm + OR2 + 4608 + o1, v[2], v[3]);
        }
        __syncthreads();

        // ---- G1: L0 mix  leaky(K0 @ R2) -> R3.B   M=64 N=16 (banded)
        if (warp < 8) {
            const int m0 = (warp >> 1) * 16, n0 = (warp & 1) * 8;
            int ktlo = max(0, m0 - R0) >> 4, kthi = min(63, m0 + 15 + R0) >> 4;
            float acc[1][4] = {};
            tileN<true, 1>(acc, sm + OKH, sm + OKL, 72, m0,
                           sm + OR2, sm + OR2 + 4608, 72, n0, ktlo, kthi, lane);
            float v[4];
            #pragma unroll
            for (int cr = 0; cr < 4; cr++) v[cr] = lrelu(acc[0][cr]);
            int r0 = m0 + erow, n = n0 + ecol;
            bsplit2(sm + OR3 + r0 * 72 + n, sm + OR3 + 4608 + r0 * 72 + n, v[0], v[1]);
            bsplit2(sm + OR3 + (r0 + 8) * 72 + n, sm + OR3 + 4608 + (r0 + 8) * 72 + n, v[2], v[3]);
        }
        __syncthreads();

        // ---- G2: L1 mix  K1 @ R3 -> R2.A [s*64+h][c] (+zero pad c8..15)
        if (warp < 8) {
            const int m0 = (warp >> 1) * 16, n0 = (warp & 1) * 8;
            int ktlo = max(0, m0 - R1b) >> 4, kthi = min(63, m0 + 15 + R1b) >> 4;
            float acc[1][4] = {};
            tileN<true, 1>(acc, sm + OKH + 4608, sm + OKL + 4608, 72, m0,
                           sm + OR3, sm + OR3 + 4608, 72, n0, ktlo, kthi, lane);
            int n = n0 + ecol;
            int s = n >> 3, c = n & 7;
            int r0 = m0 + erow;
            int o0 = (s * 64 + r0) * 40 + c;
            int o1 = (s * 64 + r0 + 8) * 40 + c;
            bsplit2(sm + OR2 + o0, sm + OR2 + 5120 + o0, acc[0][0], acc[0][1]);
            bsplit2(sm + OR2 + o1, sm + OR2 + 5120 + o1, acc[0][2], acc[0][3]);
        }
        if (tid < 256) {
            int row = tid >> 1, pl = tid & 1;
            uint4 z = make_uint4(0, 0, 0, 0);
            *(uint4*)(sm + OR2 + pl * 5120 + row * 40 + 8) = z;
        }
        __syncthreads();

        // ---- G3: L1 wmult  leaky(R2.A @ W1 + b1) -> R3.B  M=128 K=16 N=16
        if (warp < 8) {
            const int m0 = warp * 16;
            float acc[2][4] = {};
            tileN<false, 2>(acc, sm + OR2, sm + OR2 + 5120, 40, m0,
                            sm + OW1H, sm + OW1L, 16, 0, 0, 0, lane);
            int r0 = m0 + erow;
            int s = r0 >> 6;
            #pragma unroll
            for (int n = 0; n < 2; n++) {
                float v[4];
                #pragma unroll
                for (int cr = 0; cr < 4; cr++)
                    v[cr] = lrelu(acc[n][cr] + sBias[8 + n * 8 + ecol + (cr & 1)]);
                int col = n * 8 + ecol;
                int o0 = (r0 & 63) * 72 + s * 16 + col;
                int o1 = ((r0 + 8) & 63) * 72 + s * 16 + col;
                bsplit2(sm + OR3 + o0, sm + OR3 + 4608 + o0, v[0], v[1]);
                bsplit2(sm + OR3 + o1, sm + OR3 + 4608 + o1, v[2], v[3]);
            }
        }
        __syncthreads();

        // ---- G4: L2 mix  K2 @ R3 -> R2.A  M=64 N=32 (banded)
        if (warp < 8) {
            const int m0 = (warp & 3) * 16, n0 = (warp >> 2) * 16;
            int ktlo = max(0, m0 - R2b) >> 4, kthi = min(63, m0 + 15 + R2b) >> 4;
            float acc[2][4] = {};
            tileN<true, 2>(acc, sm + OKH + 2 * 4608, sm + OKL + 2 * 4608, 72, m0,
                           sm + OR3, sm + OR3 + 4608, 72, n0, ktlo, kthi, lane);
            int r0 = m0 + erow;
            #pragma unroll
            for (int n = 0; n < 2; n++) {
                int nf = n0 + n * 8 + ecol;
                int s = nf >> 4, c = nf & 15;
                int o0 = (s * 64 + r0) * 40 + c;
                int o1 = (s * 64 + r0 + 8) * 40 + c;
                bsplit2(sm + OR2 + o0, sm + OR2 + 5120 + o0, acc[n][0], acc[n][1]);
                bsplit2(sm + OR2 + o1, sm + OR2 + 5120 + o1, acc[n][2], acc[n][3]);
            }
        }
        __syncthreads();

        // ---- G5: L2 wmult  leaky(R2.A @ W2 + b2) -> R3.B  M=128 K=16 N=32
        {
            const int m0 = (warp & 7) * 16, n0 = (warp >> 3) * 16;
            float acc[2][4] = {};
            tileN<false, 2>(acc, sm + OR2, sm + OR2 + 5120, 40, m0,
                            sm + OW2H, sm + OW2L, 16, n0, 0, 0, lane);
            int r0 = m0 + erow;
            int s = r0 >> 6;
            #pragma unroll
            for (int n = 0; n < 2; n++) {
                float v[4];
                #pragma unroll
                for (int cr = 0; cr < 4; cr++)
                    v[cr] = lrelu(acc[n][cr] + sBias[24 + n0 + n * 8 + ecol + (cr & 1)]);
                int col = n0 + n * 8 + ecol;
                int o0 = (r0 & 63) * 72 + s * 32 + col;
                int o1 = ((r0 + 8) & 63) * 72 + s * 32 + col;
                bsplit2(sm + OR3 + o0, sm + OR3 + 4608 + o0, v[0], v[1]);
                bsplit2(sm + OR3 + o1, sm + OR3 + 4608 + o1, v[2], v[3]);
            }
        }
        __syncthreads();

        // ---- G6: L3 mix  K3 @ R3 -> R1.A [s*64+h][c] (stride 72)  M=64 N=64
        {
            const int m0 = (warp & 3) * 16, n0 = (warp >> 2) * 16;
            int ktlo = max(0, m0 - R3b) >> 4, kthi = min(63, m0 + 15 + R3b) >> 4;
            float acc[2][4] = {};
            tileN<true, 2>(acc, sm + OKH + 3 * 4608, sm + OKL + 3 * 4608, 72, m0,
                           sm + OR3, sm + OR3 + 4608, 72, n0, ktlo, kthi, lane);
            int r0 = m0 + erow;
            #pragma unroll
            for (int n = 0; n < 2; n++) {
                int nf = n0 + n * 8 + ecol;
                int s = nf >> 5, c = nf & 31;
                int o0 = (s * 64 + r0) * 72 + c;
                int o1 = (s * 64 + r0 + 8) * 72 + c;
                bsplit2(sm + OR1H + o0, sm + OR1L + o0, acc[n][0], acc[n][1]);
                bsplit2(sm + OR1H + o1, sm + OR1L + o1, acc[n][2], acc[n][3]);
            }
        }
        __syncthreads();

        // ---- G7: L3 wmult  leaky(R1.A @ W3 + b3) -> hi plane R2, lo plane R3
        {
            const int m0 = (warp & 7) * 16, n0 = (warp >> 3) * 32;
            float acc[4][4] = {};
            tileN<false, 4>(acc, sm + OR1H, sm + OR1L, 72, m0,
                            sm + OW3H, sm + OW3L, 40, n0, 0, 1, lane);
            int r0 = m0 + erow;
            #pragma unroll
            for (int n = 0; n < 4; n++) {
                float v[4];
                #pragma unroll
                for (int cr = 0; cr < 4; cr++)
                    v[cr] = lrelu(acc[n][cr] + sBias[56 + n0 + n * 8 + ecol + (cr & 1)]);
                int col = n0 + n * 8 + ecol;
                int o0 = r0 * 72 + col;
                int o1 = (r0 + 8) * 72 + col;
                bsplit2(sm + OR2 + o0, sm + OR3 + o0, v[0], v[1]);
                bsplit2(sm + OR2 + o1, sm + OR3 + o1, v[2], v[3]);
            }
        }
        __syncthreads();

        // ---- copy out planes -> g_h[kb=h][b][64] (16B stores) ----
        for (int idx = tid; idx < 1024; idx += 512) {
            int row = idx >> 3, ch = idx & 7;
            int s = row >> 6, h = row & 63;
            size_t go = ((size_t)h * 16384 + (gb + s)) * 64 + ch * 8;
            *(uint4*)(g_hHi + go) = *(const uint4*)(sm + OR2 + row * 72 + ch * 8);
            *(uint4*)(g_hLo + go) = *(const uint4*)(sm + OR3 + row * 72 + ch * 8);
        }
        __syncthreads();
    }
}

// ---------------------------------------------------------------------------
// Kernel C: tensor-core compress MLP, cp.async.bulk (128B rows) + mbarrier
// stages (kills the LDGSTS 16B issue ceiling that capped it at 2.1TB/s).
// ---------------------------------------------------------------------------
#define KC_STAGE_H   29952
#define KC_SA_H      0
#define KC_SA_L      9216
#define KC_SW_H      18432
#define KC_SW_L      24192
#define KC_F32_OFF   119808
#define KC_MBAR_OFF  (KC_F32_OFF + 21056)
#define KC_SMEM_BYTES (KC_MBAR_OFF + 16)
#define KC_TX_BYTES  (416u * 128u)

__global__ __launch_bounds__(256) void kernC(const float* __restrict__ bm0,
                                             const float* __restrict__ wm1,
                                             const float* __restrict__ bm1,
                                             float* __restrict__ out)
{
    extern __shared__ __align__(16) char smc[];
    bf16* sh = (bf16*)smc;
    float* fpers = (float*)(smc + KC_F32_OFF);
    float* sWm1t = fpers;            // [80][64]
    float* sBm0  = fpers + 5120;
    float* sBm1  = fpers + 5200;
    float* sOut1 = (float*)smc;      // [128][84] after k-loop

    const int tid  = threadIdx.x;
    const int lane = tid & 31;
    const int warp = tid >> 5;
    const int wm = warp >> 1, wn = warp & 1;
    const int m0 = blockIdx.x * 128;

    unsigned smem_base = (unsigned)__cvta_generic_to_shared(smc);
    unsigned mbar[2] = { smem_base + KC_MBAR_OFF, smem_base + KC_MBAR_OFF + 8 };

    for (int idx = tid; idx < 4800; idx += 256) {
        int o = idx / 80, c = idx % 80;
        sWm1t[c * 64 + o] = wm1[idx];
    }
    if (tid < 80) sBm0[tid] = bm0[tid];
    if (tid < 60) sBm1[tid] = bm1[tid];
    if (tid == 0) { mb_init(mbar[0], 1); mb_init(mbar[1], 1); }
    __syncthreads();

    // bulk stage loader: 416 x 128B row copies into padded smem (stride 144B)
    auto load_stage = [&](int kb, int st) {
        bf16* base = sh + st * KC_STAGE_H;
        unsigned mb = mbar[st];
        const bf16* Ah = g_hHi + ((size_t)kb * 16384 + m0) * 64;
        const bf16* Al = g_hLo + ((size_t)kb * 16384 + m0) * 64;
        const bf16* Wh = g_wHi + (size_t)kb * 5120;
        const bf16* Wl = g_wLo + (size_t)kb * 5120;
        for (int i = tid; i < 416; i += 256) {
            if (i < 128)      bulk128(base + KC_SA_H + i * 72, Ah + i * 64, mb);
            else if (i < 256) { int r = i - 128; bulk128(base + KC_SA_L + r * 72, Al + r * 64, mb); }
            else if (i < 336) { int r = i - 256; bulk128(base + KC_SW_H + r * 72, Wh + r * 64, mb); }
            else              { int r = i - 336; bulk128(base + KC_SW_L + r * 72, Wl + r * 64, mb); }
        }
    };

    float acc[2][5][4];
    #pragma unroll
    for (int i = 0; i < 2; i++)
        #pragma unroll
        for (int j = 0; j < 5; j++)
            #pragma unroll
            for (int k = 0; k < 4; k++) acc[i][j][k] = 0.f;

    if (tid == 0) mb_expect(mbar[0], KC_TX_BYTES);
    load_stage(0, 0);

    const int aq  = lane >> 3;
    const int arn = lane & 7;
    const int a_row_off = (aq & 1) * 8 + arn;
    const int a_col_off = (aq >> 1) * 8;
    const int bl  = lane & 15;
    const int b_rn = bl & 7;
    const int b_hi8 = (bl >> 3) * 8;

    int ph[2] = {0, 0};
    const int NK = 64;
    for (int kb = 0; kb < NK; kb++) {
        const int st = kb & 1;
        if (kb + 1 < NK) {
            if (tid == 0) mb_expect(mbar[st ^ 1], KC_TX_BYTES);
            load_stage(kb + 1, st ^ 1);
        }
        mb_wait(mbar[st], ph[st]);
        ph[st] ^= 1;

        bf16* base = sh + st * KC_STAGE_H;
        bf16* sAh = base + KC_SA_H;
        bf16* sAl = base + KC_SA_L;
        bf16* sWh = base + KC_SW_H;
        bf16* sWl = base + KC_SW_L;

        #pragma unroll
        for (int sub = 0; sub < 4; sub++) {
            const int kc = sub * 16;
            unsigned bh[5][2], blo[5][2];
            #pragma unroll
            for (int n = 0; n < 5; n++) {
                const int brow = wn * 40 + n * 8 + b_rn;
                ldx2(bh[n],  sWh + brow * 72 + kc + b_hi8);
                ldx2(blo[n], sWl + brow * 72 + kc + b_hi8);
            }
            #pragma unroll
            for (int tmt = 0; tmt < 2; tmt++) {
                const int arow = wm * 32 + tmt * 16 + a_row_off;
                unsigned ah[4], al[4];
                ldx4(ah, sAh + arow * 72 + kc + a_col_off);
                ldx4(al, sAl + arow * 72 + kc + a_col_off);
                #pragma unroll
                for (int n = 0; n < 5; n++) {
                    hmma(acc[tmt][n], ah, bh[n]);
                    hmma(acc[tmt][n], ah, blo[n]);
                    hmma(acc[tmt][n], al, bh[n]);
                }
            }
        }
        __syncthreads();
    }

    #pragma unroll
    for (int tmt = 0; tmt < 2; tmt++)
        #pragma unroll
        for (int n = 0; n < 5; n++)
            #pragma unroll
            for (int cr = 0; cr < 4; cr++) {
                int row = wm * 32 + tmt * 16 + (lane >> 2) + ((cr >= 2) ? 8 : 0);
                int col = wn * 40 + n * 8 + (lane & 3) * 2 + (cr & 1);
                float v = acc[tmt][n][cr] + sBm0[col];
                v = v > 0.f ? v : v * NEG;
                sOut1[row * 84 + col] = v;
            }
    __syncthreads();

    {
        const int tr = tid >> 4;
        const int tc = tid & 15;
        float a2[8][4];
        #pragma unroll
        for (int i = 0; i < 8; i++)
            #pragma unroll
            for (int j = 0; j < 4; j++) a2[i][j] = 0.f;
        for (int c = 0; c < 80; c++) {
            float wv[4];
            #pragma unroll
            for (int j = 0; j < 4; j++) {
                int o = tc * 4 + j;
                wv[j] = (o < 60) ? sWm1t[c * 64 + o] : 0.f;
            }
            #pragma unroll
            for (int i = 0; i < 8; i++) {
                float cv = sOut1[(tr + 16 * i) * 84 + c];
                #pragma unroll
                for (int j = 0; j < 4; j++)
                    a2[i][j] = fmaf(cv, wv[j], a2[i][j]);
            }
        }
        #pragma unroll
        for (int i = 0; i < 8; i++)
            #pragma unroll
            for (int j = 0; j < 4; j++) {
                int o = tc * 4 + j;
                if (o < 60) {
                    float v = a2[i][j] + sBm1[o];
                    v = v > 0.f ? v : v * NEG;
                    out[(size_t)(m0 + tr + 16 * i) * 60 + o] = v;
                }
            }
    }
}

// ---------------------------------------------------------------------------
extern "C" void kernel_launch(void* const* d_in, const int* in_sizes, int n_in,
                              void* d_out, int out_size) {
    (void)in_sizes; (void)n_in; (void)out_size;
    const float* x   = (const float*)d_in[0];
    const float* w0  = (const float*)d_in[1];
    const float* b0  = (const float*)d_in[2];
    const float* s0  = (const float*)d_in[3];
    const float* w1  = (const float*)d_in[4];
    const float* b1  = (const float*)d_in[5];
    const float* s1  = (const float*)d_in[6];
    const float* w2  = (const float*)d_in[7];
    const float* b2  = (const float*)d_in[8];
    const float* s2  = (const float*)d_in[9];
    const float* w3  = (const float*)d_in[10];
    const float* b3  = (const float*)d_in[11];
    const float* s3  = (const float*)d_in[12];
    const float* wm0 = (const float*)d_in[13];
    const float* bm0 = (const float*)d_in[14];
    const float* wm1 = (const float*)d_in[15];
    const float* bm1 = (const float*)d_in[16];
    float* out = (float*)d_out;

    static int attr_done = 0;
    if (!attr_done) {
        cudaFuncSetAttribute(kernG, cudaFuncAttributeMaxDynamicSharedMemorySize, KG_SMEM_BYTES);
        cudaFuncSetAttribute(kernC, cudaFuncAttributeMaxDynamicSharedMemorySize, KC_SMEM_BYTES);
        attr_done = 1;
    }

    kernK<<<1, 256>>>(s0, s1, s2, s3);
    kernT<<<1280, 256>>>(wm0);
    kernG<<<1024, 512, KG_SMEM_BYTES>>>(x, w0, b0, w1, b1, w2, b2, w3, b3);
    kernC<<<128, 256, KC_SMEM_BYTES>>>(bm0, wm1, bm1, out);
}

// round 16
// speedup vs baseline: 1.2799x; 1.2799x over previous
#include <cuda_runtime.h>
#include <cuda_bf16.h>
#include <math.h>

#define NEG 0.01f
typedef __nv_bfloat16 bf16;

// ---------------------------------------------------------------------------
// Scratch (allocation-free rule: __device__ globals)
// g_hHi/g_hLo layout: [64 kb][16384 b][64], 16B chunks XOR-swizzled by (b&7)
// g_wHi/g_wLo layout: [64 kb][80 o][64],   16B chunks XOR-swizzled by (o&7)
// => kernC stages are contiguous (A: 16KB, W: 10KB) AND ldmatrix-conflict-free.
// ---------------------------------------------------------------------------
__device__ __align__(16) float g_K[4 * 64 * 64];
__device__ int g_band[4];
__device__ __align__(16) bf16 g_wHi[64 * 80 * 64];
__device__ __align__(16) bf16 g_wLo[64 * 80 * 64];
__device__ __align__(16) bf16 g_hHi[(size_t)64 * 16384 * 64];
__device__ __align__(16) bf16 g_hLo[(size_t)64 * 16384 * 64];

// ---------------------------------------------------------------------------
// Kernel K: build 4 L1-normalized gaussian mixing matrices + band radii
// ---------------------------------------------------------------------------
__global__ void kernK(const float* __restrict__ s0, const float* __restrict__ s1,
                      const float* __restrict__ s2, const float* __restrict__ s3) {
    int t = threadIdx.x;
    int l = t >> 6, i = t & 63;
    float sg = (l == 0) ? s0[0] : (l == 1) ? s1[0] : (l == 2) ? s2[0] : s3[0];
    float denom = 2.0f * sg * sg;
    float sum = 0.0f;
    for (int j = 0; j < 64; j++) {
        float d = (float)(i - j);
        sum += expf(-(d * d) / denom);
    }
    sum = fmaxf(sum, 1e-12f);
    for (int j = 0; j < 64; j++) {
        float d = (float)(i - j);
        g_K[(l * 64 + i) * 64 + j] = expf(-(d * d) / denom) / sum;
    }
    if (i == 0) {
        float rr = sqrtf(fmaxf(denom, 0.0f) * 18.5f);
        int R = (int)rr + 1;
        if (R > 63) R = 63;
        g_band[l] = R;
    }
}

// ---------------------------------------------------------------------------
// Kernel T: split wm0 [80][4096] -> bf16 hi/lo, [kb][o][64] swizzled layout
// ---------------------------------------------------------------------------
__global__ void kernT(const float* __restrict__ wm0) {
    int idx = blockIdx.x * blockDim.x + threadIdx.x;
    if (idx >= 80 * 4096) return;
    int o = idx >> 12, k = idx & 4095;
    int kb = k >> 6, c = k & 63;
    float v = wm0[idx];
    bf16 hi = __float2bfloat16_rn(v);
    bf16 lo = __float2bfloat16_rn(v - __bfloat162float(hi));
    int dst = kb * 5120 + o * 64 + ((((c >> 3) ^ (o & 7)) << 3) | (c & 7));
    g_wHi[dst] = hi;
    g_wLo[dst] = lo;
}

// ---------------------------------------------------------------------------
// mma / mbarrier / bulk-copy helpers
// ---------------------------------------------------------------------------
__device__ __forceinline__ void ldx4(unsigned r[4], const bf16* p) {
    unsigned a = (unsigned)__cvta_generic_to_shared(p);
    asm volatile("ldmatrix.sync.aligned.m8n8.x4.shared.b16 {%0,%1,%2,%3}, [%4];"
                 : "=r"(r[0]), "=r"(r[1]), "=r"(r[2]), "=r"(r[3]) : "r"(a));
}
__device__ __forceinline__ void ldx2(unsigned r[2], const bf16* p) {
    unsigned a = (unsigned)__cvta_generic_to_shared(p);
    asm volatile("ldmatrix.sync.aligned.m8n8.x2.shared.b16 {%0,%1}, [%2];"
                 : "=r"(r[0]), "=r"(r[1]) : "r"(a));
}
__device__ __forceinline__ void ldx2t(unsigned r[2], const bf16* p) {
    unsigned a = (unsigned)__cvta_generic_to_shared(p);
    asm volatile("ldmatrix.sync.aligned.m8n8.x2.trans.shared.b16 {%0,%1}, [%2];"
                 : "=r"(r[0]), "=r"(r[1]) : "r"(a));
}
__device__ __forceinline__ void hmma(float c[4], const unsigned a[4], const unsigned b[2]) {
    asm volatile("mma.sync.aligned.m16n8k16.row.col.f32.bf16.bf16.f32 "
                 "{%0,%1,%2,%3}, {%4,%5,%6,%7}, {%8,%9}, {%0,%1,%2,%3};"
                 : "+f"(c[0]), "+f"(c[1]), "+f"(c[2]), "+f"(c[3])
                 : "r"(a[0]), "r"(a[1]), "r"(a[2]), "r"(a[3]), "r"(b[0]), "r"(b[1]));
}
__device__ __forceinline__ float lrelu(float v) { return v > 0.f ? v : v * NEG; }
__device__ __forceinline__ void bsplit(bf16* hp, bf16* lp, float v) {
    bf16 h = __float2bfloat16_rn(v);
    *hp = h;
    *lp = __float2bfloat16_rn(v - __bfloat162float(h));
}
__device__ __forceinline__ void bsplit2(bf16* hp, bf16* lp, float v0, float v1) {
    __nv_bfloat162 h = __floats2bfloat162_rn(v0, v1);
    float r0 = v0 - __bfloat162float(h.x);
    float r1 = v1 - __bfloat162float(h.y);
    __nv_bfloat162 l = __floats2bfloat162_rn(r0, r1);
    *(__nv_bfloat162*)hp = h;
    *(__nv_bfloat162*)lp = l;
}
__device__ __forceinline__ void mb_init(unsigned a, unsigned cnt) {
    asm volatile("mbarrier.init.shared.b64 [%0], %1;" :: "r"(a), "r"(cnt) : "memory");
}
__device__ __forceinline__ void mb_expect(unsigned a, unsigned tx) {
    asm volatile("mbarrier.arrive.expect_tx.shared.b64 _, [%0], %1;" :: "r"(a), "r"(tx) : "memory");
}
__device__ __forceinline__ void mb_wait(unsigned a, unsigned ph) {
    unsigned done;
    do {
        asm volatile("{\n\t.reg .pred p;\n\t"
                     "mbarrier.try_wait.parity.acquire.cta.shared::cta.b64 p, [%1], %2, 0x989680;\n\t"
                     "selp.b32 %0, 1, 0, p;\n\t}"
                     : "=r"(done) : "r"(a), "r"(ph) : "memory");
    } while (!done);
}
__device__ __forceinline__ void bulkN(bf16* dst, const bf16* src, unsigned bytes, unsigned mb) {
    unsigned d = (unsigned)__cvta_generic_to_shared(dst);
    asm volatile("cp.async.bulk.shared::cluster.global.mbarrier::complete_tx::bytes "
                 "[%0], [%1], %2, [%3];"
                 :: "r"(d), "l"(src), "r"(bytes), "r"(mb) : "memory");
}

// Accumulate NT 16x8 tiles sharing one A-fragment load per k-tile.
// All 3 split terms (AhBh + AhBl + AlBh) go into ONE accumulator per tile.
template <bool BT, int NT>
__device__ __forceinline__ void tileN(float (*acc)[4],
                                      const bf16* Ah, const bf16* Al, int lda, int m0,
                                      const bf16* Bh, const bf16* Bl, int ldb, int n0,
                                      int ktlo, int kthi, int lane) {
    const int arow = m0 + (lane & 7) + ((lane >> 3) & 1) * 8;
    const int acol = (lane >> 4) * 8;
    for (int kt = ktlo; kt <= kthi; kt++) {
        const int kc = kt * 16;
        unsigned ah[4], al[4];
        ldx4(ah, Ah + arow * lda + kc + acol);
        ldx4(al, Al + arow * lda + kc + acol);
        #pragma unroll
        for (int n = 0; n < NT; n++) {
            const int nn = n0 + n * 8;
            unsigned bh[2], bl[2];
            if (BT) {
                const int br = kc + (lane & 15);
                ldx2t(bh, Bh + br * ldb + nn);
                ldx2t(bl, Bl + br * ldb + nn);
            } else {
                const int br = nn + (lane & 7);
                const int bc = kc + ((lane >> 3) & 1) * 8;
                ldx2(bh, Bh + br * ldb + bc);
                ldx2(bl, Bl + br * ldb + bc);
            }
            hmma(acc[n], ah, bh);
            hmma(acc[n], ah, bl);
            hmma(acc[n], al, bh);
        }
    }
}

// ---------------------------------------------------------------------------
// Kernel G (tensor-core): fused 4-layer gaussian stack.
// 512 threads / 16 warps; block = 16 samples as 8 groups of S=2; register
// prefetch of next group's x. Warp-tiles widened (NT) for A-fragment reuse.
// ---------------------------------------------------------------------------
#define OKH   0
#define OKL   18432
#define OR1H  36864
#define OR1L  46080
#define OR2   55296
#define OR3   65536
#define OW0H  75776
#define OW0L  76352
#define OW1H  76928
#define OW1L  77184
#define OW2H  77440
#define OW2L  77952
#define OW3H  78464
#define OW3L  81024
#define OHALVES 83584
#define KG_SMEM_BYTES (OHALVES * 2 + 480)

__global__ __launch_bounds__(512) void kernG(
    const float* __restrict__ x,
    const float* __restrict__ w0, const float* __restrict__ b0,
    const float* __restrict__ w1, const float* __restrict__ b1,
    const float* __restrict__ w2, const float* __restrict__ b2,
    const float* __restrict__ w3, const float* __restrict__ b3)
{
    extern __shared__ __align__(16) bf16 sm[];
    float* sBias = (float*)(sm + OHALVES);   // b0@0, b1@8, b2@24, b3@56

    const int tid = threadIdx.x;
    const int lane = tid & 31;
    const int warp = tid >> 5;
    const int R0 = g_band[0], R1b = g_band[1], R2b = g_band[2], R3b = g_band[3];

    const float4* xb4 = (const float4*)x;
    float4 xr[4];
    {
        const int gb = blockIdx.x * 16;
        #pragma unroll
        for (int k = 0; k < 4; k++) {
            int idx = tid + k * 512;
            xr[k] = xb4[(size_t)(gb + (idx >> 10)) * 1024 + (idx & 1023)];
        }
    }

    // ---- one-time staging ----
    for (int idx = tid; idx < 16384; idx += 512) {
        int l = idx >> 12, i = (idx >> 6) & 63, j = idx & 63;
        bsplit(sm + OKH + l * 4608 + i * 72 + j, sm + OKL + l * 4608 + i * 72 + j, g_K[idx]);
    }
    if (tid < 512) {
        int o = tid >> 6, c = tid & 63;
        bsplit(sm + OW0H + o * 72 + c, sm + OW0L + o * 72 + c, w0[tid]);
    }
    if (tid < 256) {
        int o = tid >> 4, c = tid & 15;
        float v = (c < 8) ? w1[o * 8 + c] : 0.f;
        bsplit(sm + OW1H + o * 16 + c, sm + OW1L + o * 16 + c, v);
    }
    if (tid < 512) {
        int o = tid >> 4, c = tid & 15;
        bsplit(sm + OW2H + o * 16 + c, sm + OW2L + o * 16 + c, w2[tid]);
    }
    for (int idx = tid; idx < 2048; idx += 512) {
        int o = idx >> 5, c = idx & 31;
        bsplit(sm + OW3H + o * 40 + c, sm + OW3L + o * 40 + c, w3[idx]);
    }
    if (tid < 8) sBias[tid] = b0[tid];
    else if (tid >= 32 && tid < 48) sBias[8 + tid - 32] = b1[tid - 32];
    else if (tid >= 64 && tid < 96) sBias[24 + tid - 64] = b2[tid - 64];
    else if (tid >= 128 && tid < 192) sBias[56 + tid - 128] = b3[tid - 128];
    __syncthreads();

    const int erow = lane >> 2;
    const int ecol = (lane & 3) * 2;

    for (int g = 0; g < 8; g++) {
        const int gb = blockIdx.x * 16 + g * 2;

        // ---- split prefetched X regs -> R1 (A-layout [s*64+h][72]) ----
        #pragma unroll
        for (int k = 0; k < 4; k++) {
            int idx = tid + k * 512;
            int s = idx >> 10, rem = idx & 1023;
            int h = rem >> 4, c4 = rem & 15;
            int o = (s * 64 + h) * 72 + c4 * 4;
            bsplit2(sm + OR1H + o, sm + OR1L + o, xr[k].x, xr[k].y);
            bsplit2(sm + OR1H + o + 2, sm + OR1L + o + 2, xr[k].z, xr[k].w);
        }
        __syncthreads();

        if (g < 7) {
            const int gbn = gb + 2;
            #pragma unroll
            for (int k = 0; k < 4; k++) {
                int idx = tid + k * 512;
                xr[k] = xb4[(size_t)(gbn + (idx >> 10)) * 1024 + (idx & 1023)];
            }
        }

        // ---- G0: L0 wmult  M=128 K=64 N=8 : X@W0 + b0 -> R2.B [h][s*8+c]
        if (warp < 8) {
            const int m0 = warp * 16;
            float acc[1][4] = {};
            tileN<false, 1>(acc, sm + OR1H, sm + OR1L, 72, m0,
                            sm + OW0H, sm + OW0L, 72, 0, 0, 3, lane);
            float v[4];
            #pragma unroll
            for (int cr = 0; cr < 4; cr++)
                v[cr] = acc[0][cr] + sBias[ecol + (cr & 1)];
            int r0 = m0 + erow;
            int s = r0 >> 6;
            int o0 = (r0 & 63) * 72 + s * 8 + ecol;
            int o1 = ((r0 + 8) & 63) * 72 + s * 8 + ecol;
            bsplit2(sm + OR2 + o0, sm + OR2 + 4608 + o0, v[0], v[1]);
            bsplit2(sm + OR2 + o1, sm + OR2 + 4608 + o1, v[2], v[3]);
        }
        __syncthreads();

        // ---- G1: L0 mix  leaky(K0 @ R2) -> R3.B   M=64 N=16 (banded)
        if (warp < 8) {
            const int m0 = (warp >> 1) * 16, n0 = (warp & 1) * 8;
            int ktlo = max(0, m0 - R0) >> 4, kthi = min(63, m0 + 15 + R0) >> 4;
            float acc[1][4] = {};
            tileN<true, 1>(acc, sm + OKH, sm + OKL, 72, m0,
                           sm + OR2, sm + OR2 + 4608, 72, n0, ktlo, kthi, lane);
            float v[4];
            #pragma unroll
            for (int cr = 0; cr < 4; cr++) v[cr] = lrelu(acc[0][cr]);
            int r0 = m0 + erow, n = n0 + ecol;
            bsplit2(sm + OR3 + r0 * 72 + n, sm + OR3 + 4608 + r0 * 72 + n, v[0], v[1]);
            bsplit2(sm + OR3 + (r0 + 8) * 72 + n, sm + OR3 + 4608 + (r0 + 8) * 72 + n, v[2], v[3]);
        }
        __syncthreads();

        // ---- G2: L1 mix  K1 @ R3 -> R2.A [s*64+h][c] (+zero pad c8..15)
        if (warp < 8) {
            const int m0 = (warp >> 1) * 16, n0 = (warp & 1) * 8;
            int ktlo = max(0, m0 - R1b) >> 4, kthi = min(63, m0 + 15 + R1b) >> 4;
            float acc[1][4] = {};
            tileN<true, 1>(acc, sm + OKH + 4608, sm + OKL + 4608, 72, m0,
                           sm + OR3, sm + OR3 + 4608, 72, n0, ktlo, kthi, lane);
            int n = n0 + ecol;
            int s = n >> 3, c = n & 7;
            int r0 = m0 + erow;
            int o0 = (s * 64 + r0) * 40 + c;
            int o1 = (s * 64 + r0 + 8) * 40 + c;
            bsplit2(sm + OR2 + o0, sm + OR2 + 5120 + o0, acc[0][0], acc[0][1]);
            bsplit2(sm + OR2 + o1, sm + OR2 + 5120 + o1, acc[0][2], acc[0][3]);
        }
        if (tid < 256) {
            int row = tid >> 1, pl = tid & 1;
            uint4 z = make_uint4(0, 0, 0, 0);
            *(uint4*)(sm + OR2 + pl * 5120 + row * 40 + 8) = z;
        }
        __syncthreads();

        // ---- G3: L1 wmult  leaky(R2.A @ W1 + b1) -> R3.B  M=128 K=16 N=16
        if (warp < 8) {
            const int m0 = warp * 16;
            float acc[2][4] = {};
            tileN<false, 2>(acc, sm + OR2, sm + OR2 + 5120, 40, m0,
                            sm + OW1H, sm + OW1L, 16, 0, 0, 0, lane);
            int r0 = m0 + erow;
            int s = r0 >> 6;
            #pragma unroll
            for (int n = 0; n < 2; n++) {
                float v[4];
                #pragma unroll
                for (int cr = 0; cr < 4; cr++)
                    v[cr] = lrelu(acc[n][cr] + sBias[8 + n * 8 + ecol + (cr & 1)]);
                int col = n * 8 + ecol;
                int o0 = (r0 & 63) * 72 + s * 16 + col;
                int o1 = ((r0 + 8) & 63) * 72 + s * 16 + col;
                bsplit2(sm + OR3 + o0, sm + OR3 + 4608 + o0, v[0], v[1]);
                bsplit2(sm + OR3 + o1, sm + OR3 + 4608 + o1, v[2], v[3]);
            }
        }
        __syncthreads();

        // ---- G4: L2 mix  K2 @ R3 -> R2.A  M=64 N=32 (banded)
        if (warp < 8) {
            const int m0 = (warp & 3) * 16, n0 = (warp >> 2) * 16;
            int ktlo = max(0, m0 - R2b) >> 4, kthi = min(63, m0 + 15 + R2b) >> 4;
            float acc[2][4] = {};
            tileN<true, 2>(acc, sm + OKH + 2 * 4608, sm + OKL + 2 * 4608, 72, m0,
                           sm + OR3, sm + OR3 + 4608, 72, n0, ktlo, kthi, lane);
            int r0 = m0 + erow;
            #pragma unroll
            for (int n = 0; n < 2; n++) {
                int nf = n0 + n * 8 + ecol;
                int s = nf >> 4, c = nf & 15;
                int o0 = (s * 64 + r0) * 40 + c;
                int o1 = (s * 64 + r0 + 8) * 40 + c;
                bsplit2(sm + OR2 + o0, sm + OR2 + 5120 + o0, acc[n][0], acc[n][1]);
                bsplit2(sm + OR2 + o1, sm + OR2 + 5120 + o1, acc[n][2], acc[n][3]);
            }
        }
        __syncthreads();

        // ---- G5: L2 wmult  leaky(R2.A @ W2 + b2) -> R3.B  M=128 K=16 N=32
        {
            const int m0 = (warp & 7) * 16, n0 = (warp >> 3) * 16;
            float acc[2][4] = {};
            tileN<false, 2>(acc, sm + OR2, sm + OR2 + 5120, 40, m0,
                            sm + OW2H, sm + OW2L, 16, n0, 0, 0, lane);
            int r0 = m0 + erow;
            int s = r0 >> 6;
            #pragma unroll
            for (int n = 0; n < 2; n++) {
                float v[4];
                #pragma unroll
                for (int cr = 0; cr < 4; cr++)
                    v[cr] = lrelu(acc[n][cr] + sBias[24 + n0 + n * 8 + ecol + (cr & 1)]);
                int col = n0 + n * 8 + ecol;
                int o0 = (r0 & 63) * 72 + s * 32 + col;
                int o1 = ((r0 + 8) & 63) * 72 + s * 32 + col;
                bsplit2(sm + OR3 + o0, sm + OR3 + 4608 + o0, v[0], v[1]);
                bsplit2(sm + OR3 + o1, sm + OR3 + 4608 + o1, v[2], v[3]);
            }
        }
        __syncthreads();

        // ---- G6: L3 mix  K3 @ R3 -> R1.A [s*64+h][c] (stride 72)  M=64 N=64
        {
            const int m0 = (warp & 3) * 16, n0 = (warp >> 2) * 16;
            int ktlo = max(0, m0 - R3b) >> 4, kthi = min(63, m0 + 15 + R3b) >> 4;
            float acc[2][4] = {};
            tileN<true, 2>(acc, sm + OKH + 3 * 4608, sm + OKL + 3 * 4608, 72, m0,
                           sm + OR3, sm + OR3 + 4608, 72, n0, ktlo, kthi, lane);
            int r0 = m0 + erow;
            #pragma unroll
            for (int n = 0; n < 2; n++) {
                int nf = n0 + n * 8 + ecol;
                int s = nf >> 5, c = nf & 31;
                int o0 = (s * 64 + r0) * 72 + c;
                int o1 = (s * 64 + r0 + 8) * 72 + c;
                bsplit2(sm + OR1H + o0, sm + OR1L + o0, acc[n][0], acc[n][1]);
                bsplit2(sm + OR1H + o1, sm + OR1L + o1, acc[n][2], acc[n][3]);
            }
        }
        __syncthreads();

        // ---- G7: L3 wmult  leaky(R1.A @ W3 + b3) -> hi plane R2, lo plane R3
        {
            const int m0 = (warp & 7) * 16, n0 = (warp >> 3) * 32;
            float acc[4][4] = {};
            tileN<false, 4>(acc, sm + OR1H, sm + OR1L, 72, m0,
                            sm + OW3H, sm + OW3L, 40, n0, 0, 1, lane);
            int r0 = m0 + erow;
            #pragma unroll
            for (int n = 0; n < 4; n++) {
                float v[4];
                #pragma unroll
                for (int cr = 0; cr < 4; cr++)
                    v[cr] = lrelu(acc[n][cr] + sBias[56 + n0 + n * 8 + ecol + (cr & 1)]);
                int col = n0 + n * 8 + ecol;
                int o0 = r0 * 72 + col;
                int o1 = (r0 + 8) * 72 + col;
                bsplit2(sm + OR2 + o0, sm + OR3 + o0, v[0], v[1]);
                bsplit2(sm + OR2 + o1, sm + OR3 + o1, v[2], v[3]);
            }
        }
        __syncthreads();

        // ---- copy out planes -> g_h[kb=h][b][64], chunk-swizzled by (b&7) ----
        for (int idx = tid; idx < 1024; idx += 512) {
            int row = idx >> 3, ch = idx & 7;
            int s = row >> 6, h = row & 63;
            int b = gb + s;
            size_t go = ((size_t)h * 16384 + b) * 64 + ((ch ^ (b & 7)) * 8);
            *(uint4*)(g_hHi + go) = *(const uint4*)(sm + OR2 + row * 72 + ch * 8);
            *(uint4*)(g_hLo + go) = *(const uint4*)(sm + OR3 + row * 72 + ch * 8);
        }
        __syncthreads();
    }
}

// ---------------------------------------------------------------------------
// Kernel C: tensor-core compress MLP. Stages land via FOUR large
// cp.async.bulk ops (A planes 16KB contiguous, W planes 10KB contiguous)
// into flat smem (64-half rows); bank conflicts avoided by the producer-side
// XOR chunk swizzle which ldmatrix addressing undoes here.
// ---------------------------------------------------------------------------
#define KC_SA_H      0
#define KC_SA_L      8192
#define KC_SW_H      16384
#define KC_SW_L      21504
#define KC_STAGE_H   26624
#define KC_F32_OFF   106496
#define KC_MBAR_OFF  (KC_F32_OFF + 21056)
#define KC_SMEM_BYTES (KC_MBAR_OFF + 16)
#define KC_TX_BYTES  53248u

__global__ __launch_bounds__(256) void kernC(const float* __restrict__ bm0,
                                             const float* __restrict__ wm1,
                                             const float* __restrict__ bm1,
                                             float* __restrict__ out)
{
    extern __shared__ __align__(16) char smc[];
    bf16* sh = (bf16*)smc;
    float* fpers = (float*)(smc + KC_F32_OFF);
    float* sWm1t = fpers;            // [80][64]
    float* sBm0  = fpers + 5120;
    float* sBm1  = fpers + 5200;
    float* sOut1 = (float*)smc;      // [128][84] after k-loop

    const int tid  = threadIdx.x;
    const int lane = tid & 31;
    const int warp = tid >> 5;
    const int wm = warp >> 1, wn = warp & 1;
    const int m0 = blockIdx.x * 128;

    unsigned smem_base = (unsigned)__cvta_generic_to_shared(smc);
    unsigned mbar[2] = { smem_base + KC_MBAR_OFF, smem_base + KC_MBAR_OFF + 8 };

    for (int idx = tid; idx < 4800; idx += 256) {
        int o = idx / 80, c = idx % 80;
        sWm1t[c * 64 + o] = wm1[idx];
    }
    if (tid < 80) sBm0[tid] = bm0[tid];
    if (tid < 60) sBm1[tid] = bm1[tid];
    if (tid == 0) { mb_init(mbar[0], 1); mb_init(mbar[1], 1); }
    __syncthreads();

    // 4 large bulk copies per stage (single thread issues)
    auto load_stage = [&](int kb, int st) {
        if (tid == 0) {
            bf16* base = sh + st * KC_STAGE_H;
            unsigned mb = mbar[st];
            mb_expect(mb, KC_TX_BYTES);
            bulkN(base + KC_SA_H, g_hHi + ((size_t)kb * 16384 + m0) * 64, 16384u, mb);
            bulkN(base + KC_SA_L, g_hLo + ((size_t)kb * 16384 + m0) * 64, 16384u, mb);
            bulkN(base + KC_SW_H, g_wHi + (size_t)kb * 5120, 10240u, mb);
            bulkN(base + KC_SW_L, g_wLo + (size_t)kb * 5120, 10240u, mb);
        }
    };

    float acc[2][5][4];
    #pragma unroll
    for (int i = 0; i < 2; i++)
        #pragma unroll
        for (int j = 0; j < 5; j++)
            #pragma unroll
            for (int k = 0; k < 4; k++) acc[i][j][k] = 0.f;

    load_stage(0, 0);

    const int aq  = lane >> 3;
    const int arn = lane & 7;
    const int a_row_off = (aq & 1) * 8 + arn;      // arow & 7 == arn
    const int a_ch = (aq >> 1);                    // chunk offset 0/1
    const int bl  = lane & 15;
    const int b_rn = bl & 7;                       // brow & 7 == b_rn
    const int b_ch = (bl >> 3);                    // chunk offset 0/1

    int ph[2] = {0, 0};
    const int NK = 64;
    for (int kb = 0; kb < NK; kb++) {
        const int st = kb & 1;
        if (kb + 1 < NK) load_stage(kb + 1, st ^ 1);
        mb_wait(mbar[st], ph[st]);
        ph[st] ^= 1;

        bf16* base = sh + st * KC_STAGE_H;
        bf16* sAh = base + KC_SA_H;
        bf16* sAl = base + KC_SA_L;
        bf16* sWh = base + KC_SW_H;
        bf16* sWl = base + KC_SW_L;

        #pragma unroll
        for (int sub = 0; sub < 4; sub++) {
            const int ch_base = sub * 2;           // k-chunk base (16 halves = 2 chunks)
            unsigned bh[5][2], blo[5][2];
            #pragma unroll
            for (int n = 0; n < 5; n++) {
                const int brow = wn * 40 + n * 8 + b_rn;
                const int sw = ((ch_base + b_ch) ^ b_rn) * 8;
                ldx2(bh[n],  sWh + brow * 64 + sw);
                ldx2(blo[n], sWl + brow * 64 + sw);
            }
            #pragma unroll
            for (int tmt = 0; tmt < 2; tmt++) {
                const int arow = wm * 32 + tmt * 16 + a_row_off;
                const int sw = ((ch_base + a_ch) ^ arn) * 8;
                unsigned ah[4], al[4];
                ldx4(ah, sAh + arow * 64 + sw);
                ldx4(al, sAl + arow * 64 + sw);
                #pragma unroll
                for (int n = 0; n < 5; n++) {
                    hmma(acc[tmt][n], ah, bh[n]);
                    hmma(acc[tmt][n], ah, blo[n]);
                    hmma(acc[tmt][n], al, bh[n]);
                }
            }
        }
        __syncthreads();
    }

    #pragma unroll
    for (int tmt = 0; tmt < 2; tmt++)
        #pragma unroll
        for (int n = 0; n < 5; n++)
            #pragma unroll
            for (int cr = 0; cr < 4; cr++) {
                int row = wm * 32 + tmt * 16 + (lane >> 2) + ((cr >= 2) ? 8 : 0);
                int col = wn * 40 + n * 8 + (lane & 3) * 2 + (cr & 1);
                float v = acc[tmt][n][cr] + sBm0[col];
                v = v > 0.f ? v : v * NEG;
                sOut1[row * 84 + col] = v;
            }
    __syncthreads();

    {
        const int tr = tid >> 4;
        const int tc = tid & 15;
        float a2[8][4];
        #pragma unroll
        for (int i = 0; i < 8; i++)
            #pragma unroll
            for (int j = 0; j < 4; j++) a2[i][j] = 0.f;
        for (int c = 0; c < 80; c++) {
            float wv[4];
            #pragma unroll
            for (int j = 0; j < 4; j++) {
                int o = tc * 4 + j;
                wv[j] = (o < 60) ? sWm1t[c * 64 + o] : 0.f;
            }
            #pragma unroll
            for (int i = 0; i < 8; i++) {
                float cv = sOut1[(tr + 16 * i) * 84 + c];
                #pragma unroll
                for (int j = 0; j < 4; j++)
                    a2[i][j] = fmaf(cv, wv[j], a2[i][j]);
            }
        }
        #pragma unroll
        for (int i = 0; i < 8; i++)
            #pragma unroll
            for (int j = 0; j < 4; j++) {
                int o = tc * 4 + j;
                if (o < 60) {
                    float v = a2[i][j] + sBm1[o];
                    v = v > 0.f ? v : v * NEG;
                    out[(size_t)(m0 + tr + 16 * i) * 60 + o] = v;
                }
            }
    }
}

// ---------------------------------------------------------------------------
extern "C" void kernel_launch(void* const* d_in, const int* in_sizes, int n_in,
                              void* d_out, int out_size) {
    (void)in_sizes; (void)n_in; (void)out_size;
    const float* x   = (const float*)d_in[0];
    const float* w0  = (const float*)d_in[1];
    const float* b0  = (const float*)d_in[2];
    const float* s0  = (const float*)d_in[3];
    const float* w1  = (const float*)d_in[4];
    const float* b1  = (const float*)d_in[5];
    const float* s1  = (const float*)d_in[6];
    const float* w2  = (const float*)d_in[7];
    const float* b2  = (const float*)d_in[8];
    const float* s2  = (const float*)d_in[9];
    const float* w3  = (const float*)d_in[10];
    const float* b3  = (const float*)d_in[11];
    const float* s3  = (const float*)d_in[12];
    const float* wm0 = (const float*)d_in[13];
    const float* bm0 = (const float*)d_in[14];
    const float* wm1 = (const float*)d_in[15];
    const float* bm1 = (const float*)d_in[16];
    float* out = (float*)d_out;

    static int attr_done = 0;
    if (!attr_done) {
        cudaFuncSetAttribute(kernG, cudaFuncAttributeMaxDynamicSharedMemorySize, KG_SMEM_BYTES);
        cudaFuncSetAttribute(kernC, cudaFuncAttributeMaxDynamicSharedMemorySize, KC_SMEM_BYTES);
        attr_done = 1;
    }

    kernK<<<1, 256>>>(s0, s1, s2, s3);
    kernT<<<1280, 256>>>(wm0);
    kernG<<<1024, 512, KG_SMEM_BYTES>>>(x, w0, b0, w1, b1, w2, b2, w3, b3);
    kernC<<<128, 256, KC_SMEM_BYTES>>>(bm0, wm1, bm1, out);
}

// round 17
// speedup vs baseline: 1.2995x; 1.0153x over previous
#include <cuda_runtime.h>
#include <cuda_bf16.h>
#include <math.h>

#define NEG 0.01f
typedef __nv_bfloat16 bf16;

// ---------------------------------------------------------------------------
// Scratch (allocation-free rule: __device__ globals)
// g_hHi/g_hLo layout: [64 kb][16384 b][64], 16B chunks XOR-swizzled by (b&7)
// g_wHi/g_wLo layout: [64 kb][80 o][64],   16B chunks XOR-swizzled by (o&7)
// ---------------------------------------------------------------------------
__device__ __align__(16) float g_K[4 * 64 * 64];
__device__ int g_band[4];
__device__ __align__(16) bf16 g_wHi[64 * 80 * 64];
__device__ __align__(16) bf16 g_wLo[64 * 80 * 64];
__device__ __align__(16) bf16 g_hHi[(size_t)64 * 16384 * 64];
__device__ __align__(16) bf16 g_hLo[(size_t)64 * 16384 * 64];

// ---------------------------------------------------------------------------
__global__ void kernK(const float* __restrict__ s0, const float* __restrict__ s1,
                      const float* __restrict__ s2, const float* __restrict__ s3) {
    int t = threadIdx.x;
    int l = t >> 6, i = t & 63;
    float sg = (l == 0) ? s0[0] : (l == 1) ? s1[0] : (l == 2) ? s2[0] : s3[0];
    float denom = 2.0f * sg * sg;
    float sum = 0.0f;
    for (int j = 0; j < 64; j++) {
        float d = (float)(i - j);
        sum += expf(-(d * d) / denom);
    }
    sum = fmaxf(sum, 1e-12f);
    for (int j = 0; j < 64; j++) {
        float d = (float)(i - j);
        g_K[(l * 64 + i) * 64 + j] = expf(-(d * d) / denom) / sum;
    }
    if (i == 0) {
        float rr = sqrtf(fmaxf(denom, 0.0f) * 18.5f);
        int R = (int)rr + 1;
        if (R > 63) R = 63;
        g_band[l] = R;
    }
}

__global__ void kernT(const float* __restrict__ wm0) {
    int idx = blockIdx.x * blockDim.x + threadIdx.x;
    if (idx >= 80 * 4096) return;
    int o = idx >> 12, k = idx & 4095;
    int kb = k >> 6, c = k & 63;
    float v = wm0[idx];
    bf16 hi = __float2bfloat16_rn(v);
    bf16 lo = __float2bfloat16_rn(v - __bfloat162float(hi));
    int dst = kb * 5120 + o * 64 + ((((c >> 3) ^ (o & 7)) << 3) | (c & 7));
    g_wHi[dst] = hi;
    g_wLo[dst] = lo;
}

// ---------------------------------------------------------------------------
// helpers
// ---------------------------------------------------------------------------
__device__ __forceinline__ void ldx4(unsigned r[4], const bf16* p) {
    unsigned a = (unsigned)__cvta_generic_to_shared(p);
    asm volatile("ldmatrix.sync.aligned.m8n8.x4.shared.b16 {%0,%1,%2,%3}, [%4];"
                 : "=r"(r[0]), "=r"(r[1]), "=r"(r[2]), "=r"(r[3]) : "r"(a));
}
__device__ __forceinline__ void ldx2(unsigned r[2], const bf16* p) {
    unsigned a = (unsigned)__cvta_generic_to_shared(p);
    asm volatile("ldmatrix.sync.aligned.m8n8.x2.shared.b16 {%0,%1}, [%2];"
                 : "=r"(r[0]), "=r"(r[1]) : "r"(a));
}
__device__ __forceinline__ void ldx2t(unsigned r[2], const bf16* p) {
    unsigned a = (unsigned)__cvta_generic_to_shared(p);
    asm volatile("ldmatrix.sync.aligned.m8n8.x2.trans.shared.b16 {%0,%1}, [%2];"
                 : "=r"(r[0]), "=r"(r[1]) : "r"(a));
}
__device__ __forceinline__ void hmma(float c[4], const unsigned a[4], const unsigned b[2]) {
    asm volatile("mma.sync.aligned.m16n8k16.row.col.f32.bf16.bf16.f32 "
                 "{%0,%1,%2,%3}, {%4,%5,%6,%7}, {%8,%9}, {%0,%1,%2,%3};"
                 : "+f"(c[0]), "+f"(c[1]), "+f"(c[2]), "+f"(c[3])
                 : "r"(a[0]), "r"(a[1]), "r"(a[2]), "r"(a[3]), "r"(b[0]), "r"(b[1]));
}
__device__ __forceinline__ float lrelu(float v) { return v > 0.f ? v : v * NEG; }
__device__ __forceinline__ void bsplit(bf16* hp, bf16* lp, float v) {
    bf16 h = __float2bfloat16_rn(v);
    *hp = h;
    *lp = __float2bfloat16_rn(v - __bfloat162float(h));
}
__device__ __forceinline__ void bsplit2(bf16* hp, bf16* lp, float v0, float v1) {
    __nv_bfloat162 h = __floats2bfloat162_rn(v0, v1);
    float r0 = v0 - __bfloat162float(h.x);
    float r1 = v1 - __bfloat162float(h.y);
    __nv_bfloat162 l = __floats2bfloat162_rn(r0, r1);
    *(__nv_bfloat162*)hp = h;
    *(__nv_bfloat162*)lp = l;
}
__device__ __forceinline__ void mb_init(unsigned a, unsigned cnt) {
    asm volatile("mbarrier.init.shared.b64 [%0], %1;" :: "r"(a), "r"(cnt) : "memory");
}
__device__ __forceinline__ void mb_expect(unsigned a, unsigned tx) {
    asm volatile("mbarrier.arrive.expect_tx.shared.b64 _, [%0], %1;" :: "r"(a), "r"(tx) : "memory");
}
__device__ __forceinline__ void mb_wait(unsigned a, unsigned ph) {
    unsigned done;
    do {
        asm volatile("{\n\t.reg .pred p;\n\t"
                     "mbarrier.try_wait.parity.acquire.cta.shared::cta.b64 p, [%1], %2, 0x989680;\n\t"
                     "selp.b32 %0, 1, 0, p;\n\t}"
                     : "=r"(done) : "r"(a), "r"(ph) : "memory");
    } while (!done);
}
__device__ __forceinline__ void bulkN(bf16* dst, const bf16* src, unsigned bytes, unsigned mb) {
    unsigned d = (unsigned)__cvta_generic_to_shared(dst);
    asm volatile("cp.async.bulk.shared::cluster.global.mbarrier::complete_tx::bytes "
                 "[%0], [%1], %2, [%3];"
                 :: "r"(d), "l"(src), "r"(bytes), "r"(mb) : "memory");
}
#define TEAM_BAR(team) asm volatile("bar.sync %0, 256;" :: "r"((team) + 1) : "memory")

// NT 16x8 tiles sharing one A-fragment load per k-tile, 3 split terms into
// one accumulator. BT: B stored [K][N] (trans). ASW: A rows of 64 halves with
// 16B-chunk XOR swizzle by (row&7) (used for the K matrices).
template <bool BT, int NT, bool ASW>
__device__ __forceinline__ void tileN(float (*acc)[4],
                                      const bf16* Ah, const bf16* Al, int lda, int m0,
                                      const bf16* Bh, const bf16* Bl, int ldb, int n0,
                                      int ktlo, int kthi, int lane) {
    const int arow = m0 + (lane & 7) + ((lane >> 3) & 1) * 8;
    const int acol = (lane >> 4) * 8;
    for (int kt = ktlo; kt <= kthi; kt++) {
        const int kc = kt * 16;
        int aoff;
        if (ASW) aoff = arow * 64 + ((((kc + acol) >> 3) ^ (arow & 7)) << 3);
        else     aoff = arow * lda + kc + acol;
        unsigned ah[4], al[4];
        ldx4(ah, Ah + aoff);
        ldx4(al, Al + aoff);
        #pragma unroll
        for (int n = 0; n < NT; n++) {
            const int nn = n0 + n * 8;
            unsigned bh[2], bl[2];
            if (BT) {
                const int br = kc + (lane & 15);
                ldx2t(bh, Bh + br * ldb + nn);
                ldx2t(bl, Bl + br * ldb + nn);
            } else {
                const int br = nn + (lane & 7);
                const int bc = kc + ((lane >> 3) & 1) * 8;
                ldx2(bh, Bh + br * ldb + bc);
                ldx2(bl, Bl + br * ldb + bc);
            }
            hmma(acc[n], ah, bh);
            hmma(acc[n], ah, bl);
            hmma(acc[n], al, bh);
        }
    }
}

// ---------------------------------------------------------------------------
// Kernel G: fused 4-layer gaussian stack, TWO independent 8-warp teams per
// block (named barriers). Each team owns buffers + 8 samples (4 groups of 2).
// SMEM (halves): K hi 0 / lo 16384 (swizzled rows of 64) | weights 32768.. |
// team buffers @40576 (+36864/team: R1H,R1L,R2,R3 of 9216 each) | biases.
// ---------------------------------------------------------------------------
#define OW0H 32768
#define OW0L 33344
#define OW1H 33920
#define OW1L 34176
#define OW2H 34432
#define OW2L 34944
#define OW3H 35456
#define OW3L 38016
#define OTB  40576
#define KG_SMEM_BYTES (114304 * 2 + 480)

__global__ __launch_bounds__(512) void kernG(
    const float* __restrict__ x,
    const float* __restrict__ w0, const float* __restrict__ b0,
    const float* __restrict__ w1, const float* __restrict__ b1,
    const float* __restrict__ w2, const float* __restrict__ b2,
    const float* __restrict__ w3, const float* __restrict__ b3)
{
    extern __shared__ __align__(16) bf16 sm[];
    float* sBias = (float*)(sm + 114304);   // b0@0, b1@8, b2@24, b3@56

    const int tid = threadIdx.x;
    const int lane = tid & 31;
    const int warp = tid >> 5;
    const int team = warp >> 3;
    const int w = warp & 7;
    const int ttid = tid & 255;
    const int R0 = g_band[0], R1b = g_band[1], R2b = g_band[2], R3b = g_band[3];

    bf16* R1H = sm + OTB + team * 36864;   // [128][72]
    bf16* R1L = R1H + 9216;
    bf16* R2  = R1H + 18432;               // 9216: B-layout(hi 0/lo 4608) or A-layout 24-str(hi 0/lo 3072) or out plane [128][72]
    bf16* R3  = R1H + 27648;

    const float4* xb4 = (const float4*)x;
    float4 xr[8];
    {
        const int gb = blockIdx.x * 16 + team * 8;
        #pragma unroll
        for (int k = 0; k < 8; k++) {
            int idx = ttid + k * 256;
            xr[k] = xb4[(size_t)(gb + (idx >> 10)) * 1024 + (idx & 1023)];
        }
    }

    // ---- one-time staging (whole block) ----
    for (int idx = tid; idx < 16384; idx += 512) {
        int l = idx >> 12, i = (idx >> 6) & 63, j = idx & 63;
        int sw = l * 4096 + i * 64 + ((((j >> 3) ^ (i & 7)) << 3) | (j & 7));
        bsplit(sm + sw, sm + 16384 + sw, g_K[idx]);
    }
    if (tid < 512) {                       // w0 [8][64] -> [8][72]
        int o = tid >> 6, c = tid & 63;
        bsplit(sm + OW0H + o * 72 + c, sm + OW0L + o * 72 + c, w0[tid]);
    }
    if (tid < 256) {                       // w1 [16][8] -> [16][16] k-padded
        int o = tid >> 4, c = tid & 15;
        float v = (c < 8) ? w1[o * 8 + c] : 0.f;
        bsplit(sm + OW1H + o * 16 + c, sm + OW1L + o * 16 + c, v);
    }
    if (tid < 512) {                       // w2 [32][16]
        int o = tid >> 4, c = tid & 15;
        bsplit(sm + OW2H + o * 16 + c, sm + OW2L + o * 16 + c, w2[tid]);
    }
    for (int idx = tid; idx < 2048; idx += 512) {   // w3 [64][32] -> [64][40]
        int o = idx >> 5, c = idx & 31;
        bsplit(sm + OW3H + o * 40 + c, sm + OW3L + o * 40 + c, w3[idx]);
    }
    if (tid < 8) sBias[tid] = b0[tid];
    else if (tid >= 32 && tid < 48) sBias[8 + tid - 32] = b1[tid - 32];
    else if (tid >= 64 && tid < 96) sBias[24 + tid - 64] = b2[tid - 64];
    else if (tid >= 128 && tid < 192) sBias[56 + tid - 128] = b3[tid - 128];
    __syncthreads();

    const int erow = lane >> 2;
    const int ecol = (lane & 3) * 2;

    for (int g = 0; g < 4; g++) {
        const int gb = blockIdx.x * 16 + team * 8 + g * 2;

        // ---- split prefetched X -> R1 (A-layout [s*64+h][72]) ----
        #pragma unroll
        for (int k = 0; k < 8; k++) {
            int idx = ttid + k * 256;
            int s = idx >> 10, rem = idx & 1023;
            int h = rem >> 4, c4 = rem & 15;
            int o = (s * 64 + h) * 72 + c4 * 4;
            bsplit2(R1H + o, R1L + o, xr[k].x, xr[k].y);
            bsplit2(R1H + o + 2, R1L + o + 2, xr[k].z, xr[k].w);
        }
        TEAM_BAR(team);

        if (g < 3) {
            const int gbn = gb + 2;
            #pragma unroll
            for (int k = 0; k < 8; k++) {
                int idx = ttid + k * 256;
                xr[k] = xb4[(size_t)(gbn + (idx >> 10)) * 1024 + (idx & 1023)];
            }
        }

        // ---- G0: L0 wmult M=128 K=64 N=8 : X@W0+b0 -> R2.B [h][s*8+c]
        {
            const int m0 = w * 16;
            float acc[1][4] = {};
            tileN<false, 1, false>(acc, R1H, R1L, 72, m0,
                                   sm + OW0H, sm + OW0L, 72, 0, 0, 3, lane);
            float v[4];
            #pragma unroll
            for (int cr = 0; cr < 4; cr++)
                v[cr] = acc[0][cr] + sBias[ecol + (cr & 1)];
            int r0 = m0 + erow;
            int s = r0 >> 6;
            int o0 = (r0 & 63) * 72 + s * 8 + ecol;
            int o1 = ((r0 + 8) & 63) * 72 + s * 8 + ecol;
            bsplit2(R2 + o0, R2 + 4608 + o0, v[0], v[1]);
            bsplit2(R2 + o1, R2 + 4608 + o1, v[2], v[3]);
        }
        TEAM_BAR(team);

        // ---- G1: L0 mix leaky(K0 @ R2.B) -> R3.B  M=64 N=16 (banded)
        {
            const int m0 = (w >> 1) * 16, n0 = (w & 1) * 8;
            int ktlo = max(0, m0 - R0) >> 4, kthi = min(63, m0 + 15 + R0) >> 4;
            float acc[1][4] = {};
            tileN<true, 1, true>(acc, sm, sm + 16384, 64, m0,
                                 R2, R2 + 4608, 72, n0, ktlo, kthi, lane);
            float v[4];
            #pragma unroll
            for (int cr = 0; cr < 4; cr++) v[cr] = lrelu(acc[0][cr]);
            int r0 = m0 + erow, n = n0 + ecol;
            bsplit2(R3 + r0 * 72 + n, R3 + 4608 + r0 * 72 + n, v[0], v[1]);
            bsplit2(R3 + (r0 + 8) * 72 + n, R3 + 4608 + (r0 + 8) * 72 + n, v[2], v[3]);
        }
        TEAM_BAR(team);

        // ---- G2: L1 mix K1 @ R3.B -> R2.A (stride 24) + zero pad c8..15
        {
            const int m0 = (w >> 1) * 16, n0 = (w & 1) * 8;
            int ktlo = max(0, m0 - R1b) >> 4, kthi = min(63, m0 + 15 + R1b) >> 4;
            float acc[1][4] = {};
            tileN<true, 1, true>(acc, sm + 4096, sm + 16384 + 4096, 64, m0,
                                 R3, R3 + 4608, 72, n0, ktlo, kthi, lane);
            int n = n0 + ecol;
            int s = n >> 3, c = n & 7;
            int r0 = m0 + erow;
            int o0 = (s * 64 + r0) * 24 + c;
            int o1 = (s * 64 + r0 + 8) * 24 + c;
            bsplit2(R2 + o0, R2 + 3072 + o0, acc[0][0], acc[0][1]);
            bsplit2(R2 + o1, R2 + 3072 + o1, acc[0][2], acc[0][3]);
        }
        {
            int row = ttid >> 1, pl = ttid & 1;
            uint4 z = make_uint4(0, 0, 0, 0);
            *(uint4*)(R2 + pl * 3072 + row * 24 + 8) = z;
        }
        TEAM_BAR(team);

        // ---- G3: L1 wmult leaky(R2.A @ W1 + b1) -> R3.B  M=128 K=16 N=16
        {
            const int m0 = w * 16;
            float acc[2][4] = {};
            tileN<false, 2, false>(acc, R2, R2 + 3072, 24, m0,
                                   sm + OW1H, sm + OW1L, 16, 0, 0, 0, lane);
            int r0 = m0 + erow;
            int s = r0 >> 6;
            #pragma unroll
            for (int n = 0; n < 2; n++) {
                float v[4];
                #pragma unroll
                for (int cr = 0; cr < 4; cr++)
                    v[cr] = lrelu(acc[n][cr] + sBias[8 + n * 8 + ecol + (cr & 1)]);
                int col = n * 8 + ecol;
                int o0 = (r0 & 63) * 72 + s * 16 + col;
                int o1 = ((r0 + 8) & 63) * 72 + s * 16 + col;
                bsplit2(R3 + o0, R3 + 4608 + o0, v[0], v[1]);
                bsplit2(R3 + o1, R3 + 4608 + o1, v[2], v[3]);
            }
        }
        TEAM_BAR(team);

        // ---- G4: L2 mix K2 @ R3.B -> R2.A  M=64 N=32 (banded)
        {
            const int m0 = (w & 3) * 16, n0 = (w >> 2) * 16;
            int ktlo = max(0, m0 - R2b) >> 4, kthi = min(63, m0 + 15 + R2b) >> 4;
            float acc[2][4] = {};
            tileN<true, 2, true>(acc, sm + 2 * 4096, sm + 16384 + 2 * 4096, 64, m0,
                                 R3, R3 + 4608, 72, n0, ktlo, kthi, lane);
            int r0 = m0 + erow;
            #pragma unroll
            for (int n = 0; n < 2; n++) {
                int nf = n0 + n * 8 + ecol;
                int s = nf >> 4, c = nf & 15;
                int o0 = (s * 64 + r0) * 24 + c;
                int o1 = (s * 64 + r0 + 8) * 24 + c;
                bsplit2(R2 + o0, R2 + 3072 + o0, acc[n][0], acc[n][1]);
                bsplit2(R2 + o1, R2 + 3072 + o1, acc[n][2], acc[n][3]);
            }
        }
        TEAM_BAR(team);

        // ---- G5: L2 wmult leaky(R2.A @ W2 + b2) -> R3.B  M=128 K=16 N=32
        {
            const int m0 = w * 16;
            float acc[4][4] = {};
            tileN<false, 4, false>(acc, R2, R2 + 3072, 24, m0,
                                   sm + OW2H, sm + OW2L, 16, 0, 0, 0, lane);
            int r0 = m0 + erow;
            int s = r0 >> 6;
            #pragma unroll
            for (int n = 0; n < 4; n++) {
                float v[4];
                #pragma unroll
                for (int cr = 0; cr < 4; cr++)
                    v[cr] = lrelu(acc[n][cr] + sBias[24 + n * 8 + ecol + (cr & 1)]);
                int col = n * 8 + ecol;
                int o0 = (r0 & 63) * 72 + s * 32 + col;
                int o1 = ((r0 + 8) & 63) * 72 + s * 32 + col;
                bsplit2(R3 + o0, R3 + 4608 + o0, v[0], v[1]);
                bsplit2(R3 + o1, R3 + 4608 + o1, v[2], v[3]);
            }
        }
        TEAM_BAR(team);

        // ---- G6: L3 mix K3 @ R3.B -> R1.A [s*64+h][c] (stride 72) M=64 N=64
        {
            const int m0 = (w & 3) * 16, n0 = (w >> 2) * 32;
            int ktlo = max(0, m0 - R3b) >> 4, kthi = min(63, m0 + 15 + R3b) >> 4;
            float acc[4][4] = {};
            tileN<true, 4, true>(acc, sm + 3 * 4096, sm + 16384 + 3 * 4096, 64, m0,
                                 R3, R3 + 4608, 72, n0, ktlo, kthi, lane);
            int r0 = m0 + erow;
            #pragma unroll
            for (int n = 0; n < 4; n++) {
                int nf = n0 + n * 8 + ecol;
                int s = nf >> 5, c = nf & 31;
                int o0 = (s * 64 + r0) * 72 + c;
                int o1 = (s * 64 + r0 + 8) * 72 + c;
                bsplit2(R1H + o0, R1L + o0, acc[n][0], acc[n][1]);
                bsplit2(R1H + o1, R1L + o1, acc[n][2], acc[n][3]);
            }
        }
        TEAM_BAR(team);

        // ---- G7: L3 wmult leaky(R1.A @ W3 + b3) -> hi plane R2, lo plane R3
        {
            const int m0 = w * 16;
            #pragma unroll
            for (int nh = 0; nh < 2; nh++) {
                const int n0 = nh * 32;
                float acc[4][4] = {};
                tileN<false, 4, false>(acc, R1H, R1L, 72, m0,
                                       sm + OW3H, sm + OW3L, 40, n0, 0, 1, lane);
                int r0 = m0 + erow;
                #pragma unroll
                for (int n = 0; n < 4; n++) {
                    float v[4];
                    #pragma unroll
                    for (int cr = 0; cr < 4; cr++)
                        v[cr] = lrelu(acc[n][cr] + sBias[56 + n0 + n * 8 + ecol + (cr & 1)]);
                    int col = n0 + n * 8 + ecol;
                    int o0 = r0 * 72 + col;
                    int o1 = (r0 + 8) * 72 + col;
                    bsplit2(R2 + o0, R3 + o0, v[0], v[1]);
                    bsplit2(R2 + o1, R3 + o1, v[2], v[3]);
                }
            }
        }
        TEAM_BAR(team);

        // ---- copy out -> g_h[kb=h][b][64], chunk-swizzled by (b&7) ----
        for (int idx = ttid; idx < 1024; idx += 256) {
            int row = idx >> 3, ch = idx & 7;
            int s = row >> 6, h = row & 63;
            int b = gb + s;
            size_t go = ((size_t)h * 16384 + b) * 64 + ((ch ^ (b & 7)) * 8);
            *(uint4*)(g_hHi + go) = *(const uint4*)(R2 + row * 72 + ch * 8);
            *(uint4*)(g_hLo + go) = *(const uint4*)(R3 + row * 72 + ch * 8);
        }
        TEAM_BAR(team);
    }
}

// ---------------------------------------------------------------------------
// Kernel C: tensor-core compress MLP, 4 large cp.async.bulk ops per stage
// into flat smem; producer-side XOR chunk swizzle undone at ldmatrix.
// ---------------------------------------------------------------------------
#define KC_SA_H      0
#define KC_SA_L      8192
#define KC_SW_H      16384
#define KC_SW_L      21504
#define KC_STAGE_H   26624
#define KC_F32_OFF   106496
#define KC_MBAR_OFF  (KC_F32_OFF + 21056)
#define KC_SMEM_BYTES (KC_MBAR_OFF + 16)
#define KC_TX_BYTES  53248u

__global__ __launch_bounds__(256) void kernC(const float* __restrict__ bm0,
                                             const float* __restrict__ wm1,
                                             const float* __restrict__ bm1,
                                             float* __restrict__ out)
{
    extern __shared__ __align__(16) char smc[];
    bf16* sh = (bf16*)smc;
    float* fpers = (float*)(smc + KC_F32_OFF);
    float* sWm1t = fpers;
    float* sBm0  = fpers + 5120;
    float* sBm1  = fpers + 5200;
    float* sOut1 = (float*)smc;

    const int tid  = threadIdx.x;
    const int lane = tid & 31;
    const int warp = tid >> 5;
    const int wm = warp >> 1, wn = warp & 1;
    const int m0 = blockIdx.x * 128;

    unsigned smem_base = (unsigned)__cvta_generic_to_shared(smc);
    unsigned mbar[2] = { smem_base + KC_MBAR_OFF, smem_base + KC_MBAR_OFF + 8 };

    for (int idx = tid; idx < 4800; idx += 256) {
        int o = idx / 80, c = idx % 80;
        sWm1t[c * 64 + o] = wm1[idx];
    }
    if (tid < 80) sBm0[tid] = bm0[tid];
    if (tid < 60) sBm1[tid] = bm1[tid];
    if (tid == 0) { mb_init(mbar[0], 1); mb_init(mbar[1], 1); }
    __syncthreads();

    auto load_stage = [&](int kb, int st) {
        if (tid == 0) {
            bf16* base = sh + st * KC_STAGE_H;
            unsigned mb = mbar[st];
            mb_expect(mb, KC_TX_BYTES);
            bulkN(base + KC_SA_H, g_hHi + ((size_t)kb * 16384 + m0) * 64, 16384u, mb);
            bulkN(base + KC_SA_L, g_hLo + ((size_t)kb * 16384 + m0) * 64, 16384u, mb);
            bulkN(base + KC_SW_H, g_wHi + (size_t)kb * 5120, 10240u, mb);
            bulkN(base + KC_SW_L, g_wLo + (size_t)kb * 5120, 10240u, mb);
        }
    };

    float acc[2][5][4];
    #pragma unroll
    for (int i = 0; i < 2; i++)
        #pragma unroll
        for (int j = 0; j < 5; j++)
            #pragma unroll
            for (int k = 0; k < 4; k++) acc[i][j][k] = 0.f;

    load_stage(0, 0);

    const int aq  = lane >> 3;
    const int arn = lane & 7;
    const int a_row_off = (aq & 1) * 8 + arn;
    const int a_ch = (aq >> 1);
    const int bl  = lane & 15;
    const int b_rn = bl & 7;
    const int b_ch = (bl >> 3);

    int ph[2] = {0, 0};
    const int NK = 64;
    for (int kb = 0; kb < NK; kb++) {
        const int st = kb & 1;
        if (kb + 1 < NK) load_stage(kb + 1, st ^ 1);
        mb_wait(mbar[st], ph[st]);
        ph[st] ^= 1;

        bf16* base = sh + st * KC_STAGE_H;
        bf16* sAh = base + KC_SA_H;
        bf16* sAl = base + KC_SA_L;
        bf16* sWh = base + KC_SW_H;
        bf16* sWl = base + KC_SW_L;

        #pragma unroll
        for (int sub = 0; sub < 4; sub++) {
            const int ch_base = sub * 2;
            unsigned bh[5][2], blo[5][2];
            #pragma unroll
            for (int n = 0; n < 5; n++) {
                const int brow = wn * 40 + n * 8 + b_rn;
                const int sw = ((ch_base + b_ch) ^ b_rn) * 8;
                ldx2(bh[n],  sWh + brow * 64 + sw);
                ldx2(blo[n], sWl + brow * 64 + sw);
            }
            #pragma unroll
            for (int tmt = 0; tmt < 2; tmt++) {
                const int arow = wm * 32 + tmt * 16 + a_row_off;
                const int sw = ((ch_base + a_ch) ^ arn) * 8;
                unsigned ah[4], al[4];
                ldx4(ah, sAh + arow * 64 + sw);
                ldx4(al, sAl + arow * 64 + sw);
                #pragma unroll
                for (int n = 0; n < 5; n++) {
                    hmma(acc[tmt][n], ah, bh[n]);
                    hmma(acc[tmt][n], ah, blo[n]);
                    hmma(acc[tmt][n], al, bh[n]);
                }
            }
        }
        __syncthreads();
    }

    #pragma unroll
    for (int tmt = 0; tmt < 2; tmt++)
        #pragma unroll
        for (int n = 0; n < 5; n++)
            #pragma unroll
            for (int cr = 0; cr < 4; cr++) {
                int row = wm * 32 + tmt * 16 + (lane >> 2) + ((cr >= 2) ? 8 : 0);
                int col = wn * 40 + n * 8 + (lane & 3) * 2 + (cr & 1);
                float v = acc[tmt][n][cr] + sBm0[col];
                v = v > 0.f ? v : v * NEG;
                sOut1[row * 84 + col] = v;
            }
    __syncthreads();

    {
        const int tr = tid >> 4;
        const int tc = tid & 15;
        float a2[8][4];
        #pragma unroll
        for (int i = 0; i < 8; i++)
            #pragma unroll
            for (int j = 0; j < 4; j++) a2[i][j] = 0.f;
        for (int c = 0; c < 80; c++) {
            float wv[4];
            #pragma unroll
            for (int j = 0; j < 4; j++) {
                int o = tc * 4 + j;
                wv[j] = (o < 60) ? sWm1t[c * 64 + o] : 0.f;
            }
            #pragma unroll
            for (int i = 0; i < 8; i++) {
                float cv = sOut1[(tr + 16 * i) * 84 + c];
                #pragma unroll
                for (int j = 0; j < 4; j++)
                    a2[i][j] = fmaf(cv, wv[j], a2[i][j]);
            }
        }
        #pragma unroll
        for (int i = 0; i < 8; i++)
            #pragma unroll
            for (int j = 0; j < 4; j++) {
                int o = tc * 4 + j;
                if (o < 60) {
                    float v = a2[i][j] + sBm1[o];
                    v = v > 0.f ? v : v * NEG;
                    out[(size_t)(m0 + tr + 16 * i) * 60 + o] = v;
                }
            }
    }
}

// ---------------------------------------------------------------------------
extern "C" void kernel_launch(void* const* d_in, const int* in_sizes, int n_in,
                              void* d_out, int out_size) {
    (void)in_sizes; (void)n_in; (void)out_size;
    const float* x   = (const float*)d_in[0];
    const float* w0  = (const float*)d_in[1];
    const float* b0  = (const float*)d_in[2];
    const float* s0  = (const float*)d_in[3];
    const float* w1  = (const float*)d_in[4];
    const float* b1  = (const float*)d_in[5];
    const float* s1  = (const float*)d_in[6];
    const float* w2  = (const float*)d_in[7];
    const float* b2  = (const float*)d_in[8];
    const float* s2  = (const float*)d_in[9];
    const float* w3  = (const float*)d_in[10];
    const float* b3  = (const float*)d_in[11];
    const float* s3  = (const float*)d_in[12];
    const float* wm0 = (const float*)d_in[13];
    const float* bm0 = (const float*)d_in[14];
    const float* wm1 = (const float*)d_in[15];
    const float* bm1 = (const float*)d_in[16];
    float* out = (float*)d_out;

    static int attr_done = 0;
    if (!attr_done) {
        cudaFuncSetAttribute(kernG, cudaFuncAttributeMaxDynamicSharedMemorySize, KG_SMEM_BYTES);
        cudaFuncSetAttribute(kernC, cudaFuncAttributeMaxDynamicSharedMemorySize, KC_SMEM_BYTES);
        attr_done = 1;
    }

    kernK<<<1, 256>>>(s0, s1, s2, s3);
    kernT<<<1280, 256>>>(wm0);
    kernG<<<1024, 512, KG_SMEM_BYTES>>>(x, w0, b0, w1, b1, w2, b2, w3, b3);
    kernC<<<128, 256, KC_SMEM_BYTES>>>(bm0, wm1, bm1, out);
}